// round 11
// baseline (speedup 1.0000x reference)
#include <cuda_runtime.h>
#include <cstdint>

#define K_TOTAL 100000
#define KC      352
#define NB      285                           // 284*352 + 32 = 100000 exactly
#define KB      32                            // k per pipeline step
#define SEQ     64
#define G4      200
#define HID     50
#define SG      (SEQ * G4)                    // 12800

#define RGROUPS 16
#define RSPAN   18                            // 16*18 = 288 >= 285

#define XROW    36                            // padded X staging row (floats)
#define XB      3                             // X staging buffers

// Scratch (device globals)
__device__ float g_partial[NB * SG];          // 14.6 MB
__device__ float g_p2[RGROUPS * SG];

typedef unsigned long long ull;

__device__ __forceinline__ ull pack2(float a, float b) {
    ull r; asm("mov.b64 %0, {%1, %2};" : "=l"(r) : "f"(a), "f"(b)); return r;
}
__device__ __forceinline__ void fma2(ull& d, ull a, ull b) {
    asm("fma.rn.f32x2 %0, %1, %2, %0;" : "+l"(d) : "l"(a), "l"(b));
}
__device__ __forceinline__ float lo32(ull v) { return __uint_as_float((unsigned)(v & 0xffffffffu)); }
__device__ __forceinline__ float hi32(ull v) { return __uint_as_float((unsigned)(v >> 32)); }

__device__ __forceinline__ void cp_async16(float* smem, const float* gmem) {
    unsigned sa = (unsigned)__cvta_generic_to_shared(smem);
    asm volatile("cp.async.cg.shared.global [%0], [%1], 16;" :: "r"(sa), "l"(gmem));
}
__device__ __forceinline__ void cp_commit() { asm volatile("cp.async.commit_group;"); }
__device__ __forceinline__ void cp_wait1() { asm volatile("cp.async.wait_group 1;"); }
__device__ __forceinline__ void cp_wait0() { asm volatile("cp.async.wait_group 0;"); }

__device__ __forceinline__ uint32_t cvtpack(float hi_val, float lo_val) {
    uint32_t r;
    asm("cvt.rn.bf16x2.f32 %0, %1, %2;" : "=r"(r) : "f"(hi_val), "f"(lo_val));
    return r;
}

__device__ __forceinline__ void mma16816(float* d,
                                         uint32_t a0, uint32_t a1, uint32_t a2, uint32_t a3,
                                         uint32_t b0, uint32_t b1) {
    asm volatile(
        "mma.sync.aligned.m16n8k16.row.col.f32.bf16.bf16.f32 "
        "{%0,%1,%2,%3}, {%4,%5,%6,%7}, {%8,%9}, {%0,%1,%2,%3};"
        : "+f"(d[0]), "+f"(d[1]), "+f"(d[2]), "+f"(d[3])
        : "r"(a0), "r"(a1), "r"(a2), "r"(a3), "r"(b0), "r"(b1));
}

// mslot for k2 in 0..15: 8*(k2>>3) + 2*(k2&3) + ((k2&7)>>2)
__device__ __constant__ const int MS16[16] =
    {0, 2, 4, 6, 1, 3, 5, 7, 8, 10, 12, 14, 9, 11, 13, 15};

// ---------------------------------------------------------------------------
// Phase A: split-K tensor-core GEMM (bf16 split precision, 3 combos).
// 285 CTAs x 256 threads, 2 CTAs/SM. W: direct LDG->regs->bf16 STS.
// X: cp.async staging (3 bufs, padded rows). Warps: 4 m-tiles x 2 n-halves.
// ---------------------------------------------------------------------------
__global__ void __launch_bounds__(256, 2) gemm_partial(
    const float* __restrict__ x, const float* __restrict__ Wi)
{
    extern __shared__ float sm[];
    float* stgX = sm;                                   // XB x 64x36 f32
    uint32_t* cXh = (uint32_t*)(sm + XB * (64 * XROW)); // 2 x 64x18
    uint32_t* cXl = cXh + 2 * 1152;
    uint32_t* cWh = cXl + 2 * 1152;                     // 2 x 200x18
    uint32_t* cWl = cWh + 2 * 3600;

    const int t  = threadIdx.x;
    const int k0 = blockIdx.x * KC;
    const int kcnt = (K_TOTAL - k0 < KC) ? (K_TOTAL - k0) : KC;
    const int S = kcnt / KB;                            // 11 or 1

    const int warp = t >> 5, lane = t & 31;
    const int g = lane >> 2, tq = lane & 3;
    const int mt = warp >> 1;                           // 0..3
    const int nh = warp & 1;
    const int NT   = nh ? 12 : 13;
    const int nbeg = nh ? 13 : 0;

    float acc[13][4];
    #pragma unroll
    for (int b = 0; b < 13; b++)
        #pragma unroll
        for (int c = 0; c < 4; c++) acc[b][c] = 0.f;

    const int nq  = t % 50;
    const int k2b = t / 50;                             // 0..3 for t<200
    const float* wbase = Wi + ((size_t)k0 + 2 * k2b) * G4 + nq * 4;

    float4 w0[4], w1[4];

    auto ldgW = [&](int step) {
        if (t < 200 && step < S) {
            const float* bp = wbase + (size_t)step * KB * G4;
            #pragma unroll
            for (int u = 0; u < 4; u++) {
                w0[u] = *(const float4*)(bp + (size_t)(8 * u) * G4);
                w1[u] = *(const float4*)(bp + (size_t)(8 * u + 1) * G4);
            }
        }
    };

    auto cpX = [&](int step, int bx) {
        const int kg = k0 + step * KB;
        float* dX = stgX + bx * (64 * XROW);
        #pragma unroll
        for (int h = 0; h < 2; h++) {
            const int slot = t + 256 * h;
            const int row = slot >> 3, q8 = slot & 7;
            cp_async16(dX + row * XROW + q8 * 4,
                       x + (size_t)row * K_TOTAL + kg + q8 * 4);
        }
    };

    auto convert = [&](int bx, int b2) {
        if (t < 200) {
            uint32_t* whb = cWh + b2 * 3600;
            uint32_t* wlb = cWl + b2 * 3600;
            #pragma unroll
            for (int u = 0; u < 4; u++) {
                const int ms = MS16[k2b + 4 * u];
                const float* f0p = (const float*)&w0[u];
                const float* f1p = (const float*)&w1[u];
                #pragma unroll
                for (int v = 0; v < 4; v++) {
                    const int n = nq * 4 + v;
                    const float f0 = f0p[v], f1 = f1p[v];
                    const uint32_t hi = cvtpack(f1, f0);
                    const float h0 = __uint_as_float(hi << 16);
                    const float h1 = __uint_as_float(hi & 0xFFFF0000u);
                    const uint32_t lo = cvtpack(f1 - h1, f0 - h0);
                    whb[n * 18 + ms] = hi;
                    wlb[n * 18 + ms] = lo;
                }
            }
        }
        {   // X: all 256 threads, row = t>>2, q = t&3, 4 k-pairs
            const int row = t >> 2, q = t & 3;
            const float* sXb = stgX + bx * (64 * XROW) + row * XROW + 8 * q;
            uint32_t* xhb = cXh + b2 * 1152 + row * 18;
            uint32_t* xlb = cXl + b2 * 1152 + row * 18;
            #pragma unroll
            for (int j = 0; j < 4; j++) {
                const float f0 = sXb[2 * j];
                const float f1 = sXb[2 * j + 1];
                const uint32_t hi = cvtpack(f1, f0);
                const float h0 = __uint_as_float(hi << 16);
                const float h1 = __uint_as_float(hi & 0xFFFF0000u);
                const uint32_t lo = cvtpack(f1 - h1, f0 - h0);
                const int ms = MS16[4 * q + j];
                xhb[ms] = hi;
                xlb[ms] = lo;
            }
        }
    };

    auto mma_tile = [&](int b2) {
        const uint32_t* xh = cXh + b2 * 1152; const uint32_t* xl = cXl + b2 * 1152;
        const uint32_t* wh = cWh + b2 * 3600; const uint32_t* wl = cWl + b2 * 3600;
        #pragma unroll
        for (int kb = 0; kb < 16; kb += 8) {
            const int r0 = mt * 16 + g;
            const uint2 Ah0 = *(const uint2*)(xh + r0 * 18 + kb + 2 * tq);
            const uint2 Ah1 = *(const uint2*)(xh + (r0 + 8) * 18 + kb + 2 * tq);
            const uint2 Al0 = *(const uint2*)(xl + r0 * 18 + kb + 2 * tq);
            const uint2 Al1 = *(const uint2*)(xl + (r0 + 8) * 18 + kb + 2 * tq);
            #pragma unroll
            for (int i = 0; i < 13; i++) {
                if (i < NT) {
                    const int n = (nbeg + i) * 8 + g;
                    const uint2 Bh = *(const uint2*)(wh + n * 18 + kb + 2 * tq);
                    const uint2 Bl = *(const uint2*)(wl + n * 18 + kb + 2 * tq);
                    mma16816(acc[i], Ah0.x, Ah1.x, Ah0.y, Ah1.y, Bh.x, Bh.y);
                    mma16816(acc[i], Ah0.x, Ah1.x, Ah0.y, Ah1.y, Bl.x, Bl.y);
                    mma16816(acc[i], Al0.x, Al1.x, Al0.y, Al1.y, Bh.x, Bh.y);
                }
            }
        }
    };

    // ---- pipeline ----
    cpX(0, 0); cp_commit();
    if (S > 1) cpX(1, 1);
    cp_commit();
    ldgW(0);
    if (S > 1) cp_wait1(); else cp_wait0();   // this thread's X0 done
    __syncthreads();                          // ALL threads' X0 visible
    convert(0, 0);
    ldgW(1);
    __syncthreads();                          // buf0 (bf16) visible

    for (int s = 0; s < S; s++) {
        if (s + 2 < S) cpX(s + 2, (s + 2) % XB);
        cp_commit();
        cp_wait1();                           // own X(s+1) groups drained
        __syncthreads();                      // ALL X(s+1) visible
        if (s + 1 < S) {
            convert((s + 1) % XB, (s + 1) & 1);
            ldgW(s + 2);
        }
        mma_tile(s & 1);
        __syncthreads();                      // convert(s+1) published for next mma
    }

    // ---- epilogue ----
    float* pout = g_partial + (size_t)blockIdx.x * SG;
    const int r0 = mt * 16 + g;
    #pragma unroll
    for (int i = 0; i < 13; i++) {
        if (i < NT) {
            const int col = (nbeg + i) * 8 + 2 * tq;
            *(float2*)(pout + (size_t)r0 * G4 + col)       = make_float2(acc[i][0], acc[i][1]);
            *(float2*)(pout + (size_t)(r0 + 8) * G4 + col) = make_float2(acc[i][2], acc[i][3]);
        }
    }
}

// ---------------------------------------------------------------------------
// Phase B: stage-1 split-K reduce (285 -> 16)
// ---------------------------------------------------------------------------
__global__ void reduce_stage1()
{
    const int idx = blockIdx.x * blockDim.x + threadIdx.x;
    const int grp = blockIdx.y;
    if (idx >= SG) return;
    const int b0   = grp * RSPAN;
    const int bend = (b0 + RSPAN < NB) ? (b0 + RSPAN) : NB;
    float s0 = 0.f, s1 = 0.f, s2 = 0.f, s3 = 0.f;
    int b = b0;
    for (; b + 3 < bend; b += 4) {
        s0 += g_partial[(size_t)(b + 0) * SG + idx];
        s1 += g_partial[(size_t)(b + 1) * SG + idx];
        s2 += g_partial[(size_t)(b + 2) * SG + idx];
        s3 += g_partial[(size_t)(b + 3) * SG + idx];
    }
    for (; b < bend; b++) s0 += g_partial[(size_t)b * SG + idx];
    g_p2[(size_t)grp * SG + idx] = (s0 + s1) + (s2 + s3);
}

// ---------------------------------------------------------------------------
// Phase C: LSTM. 256 threads: merged reduce + bias; then 128 threads run the
// split-gate recurrence with UNIFORM barriers (all threads hit both bars).
// t<50 own gates i,f of unit t; t in [64,114) own gates g,o of unit t-64.
// ---------------------------------------------------------------------------
__device__ __forceinline__ float tanh_fast(float v) {
    float r; asm("tanh.approx.f32 %0, %1;" : "=f"(r) : "f"(v)); return r;
}
__device__ __forceinline__ float sig_fast(float v) {
    return fmaf(0.5f, tanh_fast(0.5f * v), 0.5f);
}

__global__ void __launch_bounds__(256) lstm_kernel(const float* __restrict__ Wh,
                                                   const float* __restrict__ bi,
                                                   const float* __restrict__ bh,
                                                   float* __restrict__ out)
{
    extern __shared__ float sml[];
    float* gates_s = sml;                 // SG floats (51.2 KB)
    float* hbuf    = sml + SG;            // 2 x 64 floats
    float* gbuf    = hbuf + 128;          // 128 floats: g at [j], o at [64+j]
    const int t = threadIdx.x;

    // merged reduce (16 partials) + biases -> gates_s (all 8 warps)
    {
        const float4* src = (const float4*)g_p2;
        float4* dst = (float4*)gates_s;
        for (int i4 = t; i4 < SG / 4; i4 += 256) {
            float4 a0 = make_float4(0.f, 0.f, 0.f, 0.f);
            float4 a1 = a0, a2 = a0, a3 = a0;
            #pragma unroll
            for (int b = 0; b < RGROUPS; b += 4) {
                float4 v0 = src[(size_t)(b + 0) * (SG / 4) + i4];
                float4 v1 = src[(size_t)(b + 1) * (SG / 4) + i4];
                float4 v2 = src[(size_t)(b + 2) * (SG / 4) + i4];
                float4 v3 = src[(size_t)(b + 3) * (SG / 4) + i4];
                a0.x += v0.x; a0.y += v0.y; a0.z += v0.z; a0.w += v0.w;
                a1.x += v1.x; a1.y += v1.y; a1.z += v1.z; a1.w += v1.w;
                a2.x += v2.x; a2.y += v2.y; a2.z += v2.z; a2.w += v2.w;
                a3.x += v3.x; a3.y += v3.y; a3.z += v3.z; a3.w += v3.w;
            }
            const int gbase = (i4 * 4) % G4;
            const float4 bv1 = *(const float4*)(bi + gbase);
            const float4 bv2 = *(const float4*)(bh + gbase);
            float4 r;
            r.x = (a0.x + a1.x) + (a2.x + a3.x) + bv1.x + bv2.x;
            r.y = (a0.y + a1.y) + (a2.y + a3.y) + bv1.y + bv2.y;
            r.z = (a0.z + a1.z) + (a2.z + a3.z) + bv1.z + bv2.z;
            r.w = (a0.w + a1.w) + (a2.w + a3.w) + bv1.w + bv2.w;
            dst[i4] = r;
        }
    }
    if (t < 128) { hbuf[t] = 0.f; gbuf[t] = 0.f; }
    __syncthreads();

    if (t >= 128) return;                 // warps 4-7 done (uniform: whole warps)

    const bool isIF = (t < 50);
    const bool isGO = (t >= 64 && t < 114);
    const int  j    = isIF ? t : (t - 64);
    const int  c0   = isIF ? 0 : 100;
    ull wA[25], wB[25];
    if (isIF || isGO) {
        #pragma unroll
        for (int k2 = 0; k2 < 25; k2++) {
            wA[k2] = pack2(Wh[(2 * k2) * G4 + c0 + j],      Wh[(2 * k2 + 1) * G4 + c0 + j]);
            wB[k2] = pack2(Wh[(2 * k2) * G4 + c0 + 50 + j], Wh[(2 * k2 + 1) * G4 + c0 + 50 + j]);
        }
    }

    float c = 0.f, hlast = 0.f;
    asm volatile("bar.sync 1, 128;" ::: "memory");

    for (int step = 0; step < SEQ; step++) {
        float dA = 0.f, dB = 0.f;
        if (isIF || isGO) {
            const ull* hu = (const ull*)(hbuf + (step & 1) * 64);
            const float preA = gates_s[step * G4 + c0 + j];
            const float preB = gates_s[step * G4 + c0 + 50 + j];
            ull a0 = 0ull, a1 = 0ull, b0 = 0ull, b1 = 0ull;
            #pragma unroll
            for (int k2 = 0; k2 < 24; k2 += 2) {
                const ull h0 = hu[k2], h1 = hu[k2 + 1];
                fma2(a0, h0, wA[k2]);
                fma2(a1, h1, wA[k2 + 1]);
                fma2(b0, h0, wB[k2]);
                fma2(b1, h1, wB[k2 + 1]);
            }
            fma2(a0, hu[24], wA[24]);
            fma2(b0, hu[24], wB[24]);
            dA = preA + lo32(a0) + hi32(a0) + lo32(a1) + hi32(a1);
            dB = preB + lo32(b0) + hi32(b0) + lo32(b1) + hi32(b1);
        }
        if (isGO) {
            gbuf[j]      = tanh_fast(dA);   // g
            gbuf[64 + j] = sig_fast(dB);    // o
        }
        asm volatile("bar.sync 1, 128;" ::: "memory");   // ALL threads, same point
        if (isIF) {
            const float iv = sig_fast(dA);
            const float fv = sig_fast(dB);
            c = fv * c + iv * gbuf[t];
            hlast = gbuf[64 + t] * tanh_fast(c);
            hbuf[((step + 1) & 1) * 64 + t] = hlast;
        }
        asm volatile("bar.sync 1, 128;" ::: "memory");   // ALL threads, same point
    }
    if (t < HID) out[t] = hlast;
}

// ---------------------------------------------------------------------------
extern "C" void kernel_launch(void* const* d_in, const int* in_sizes, int n_in,
                              void* d_out, int out_size)
{
    const float* x  = (const float*)d_in[0];
    const float* Wi = (const float*)d_in[1];
    const float* bi = (const float*)d_in[2];
    const float* Wh = (const float*)d_in[3];
    const float* bh = (const float*)d_in[4];
    float* out = (float*)d_out;

    (void)in_sizes; (void)n_in; (void)out_size;

    const int gemm_smem = XB * 64 * XROW * 4 + (2 * 1152 * 2 + 2 * 3600 * 2) * 4; // 103,680
    cudaFuncSetAttribute(gemm_partial, cudaFuncAttributeMaxDynamicSharedMemorySize,
                         gemm_smem);
    const int lstm_smem = (SG + 128 + 128) * 4 + 64;
    cudaFuncSetAttribute(lstm_kernel, cudaFuncAttributeMaxDynamicSharedMemorySize,
                         lstm_smem);

    gemm_partial<<<NB, 256, gemm_smem>>>(x, Wi);
    reduce_stage1<<<dim3(SG / 128, RGROUPS), 128>>>();
    lstm_kernel<<<1, 256, lstm_smem>>>(Wh, bi, bh, out);
}

// round 12
// speedup vs baseline: 1.0916x; 1.0916x over previous
#include <cuda_runtime.h>
#include <cstdint>

#define K_TOTAL 100000
#define KC      704
#define NB      143                           // 142*704 + 32 = 100000 exactly
#define KB      32                            // k per pipeline step
#define SEQ     64
#define G4      200
#define HID     50
#define SG      (SEQ * G4)                    // 12800

#define RGROUPS 16
#define RSPAN   9                             // 16*9 = 144 >= 143

#define XROW    36                            // padded X staging row (floats)

// Scratch (device globals)
__device__ float g_partial[NB * SG];          // 7.3 MB
__device__ float g_p2[RGROUPS * SG];

typedef unsigned long long ull;

__device__ __forceinline__ ull pack2(float a, float b) {
    ull r; asm("mov.b64 %0, {%1, %2};" : "=l"(r) : "f"(a), "f"(b)); return r;
}
__device__ __forceinline__ void fma2(ull& d, ull a, ull b) {
    asm("fma.rn.f32x2 %0, %1, %2, %0;" : "+l"(d) : "l"(a), "l"(b));
}
__device__ __forceinline__ ull add2(ull a, ull b) {
    ull r; asm("add.rn.f32x2 %0, %1, %2;" : "=l"(r) : "l"(a), "l"(b)); return r;
}
__device__ __forceinline__ float lo32(ull v) { return __uint_as_float((unsigned)(v & 0xffffffffu)); }
__device__ __forceinline__ float hi32(ull v) { return __uint_as_float((unsigned)(v >> 32)); }

__device__ __forceinline__ void cp_async16(float* smem, const float* gmem) {
    unsigned sa = (unsigned)__cvta_generic_to_shared(smem);
    asm volatile("cp.async.cg.shared.global [%0], [%1], 16;" :: "r"(sa), "l"(gmem));
}
__device__ __forceinline__ void cp_commit() { asm volatile("cp.async.commit_group;"); }
__device__ __forceinline__ void cp_wait2() { asm volatile("cp.async.wait_group 2;"); }

__device__ __forceinline__ uint32_t cvtpack(float hi_val, float lo_val) {
    uint32_t r;
    asm("cvt.rn.bf16x2.f32 %0, %1, %2;" : "=r"(r) : "f"(hi_val), "f"(lo_val));
    return r;
}

__device__ __forceinline__ void mma16816(float* d,
                                         uint32_t a0, uint32_t a1, uint32_t a2, uint32_t a3,
                                         uint32_t b0, uint32_t b1) {
    asm volatile(
        "mma.sync.aligned.m16n8k16.row.col.f32.bf16.bf16.f32 "
        "{%0,%1,%2,%3}, {%4,%5,%6,%7}, {%8,%9}, {%0,%1,%2,%3};"
        : "+f"(d[0]), "+f"(d[1]), "+f"(d[2]), "+f"(d[3])
        : "r"(a0), "r"(a1), "r"(a2), "r"(a3), "r"(b0), "r"(b1));
}

// mslot(j) for j in 0..7 (compile-time table): 2*(j&3) + (j>>2)
__device__ __constant__ const int MSJ[8] = {0, 2, 4, 6, 1, 3, 5, 7};

// ---------------------------------------------------------------------------
// Phase A: split-K tensor-core GEMM (bf16 split precision, 3 combos).
// 143 CTAs x 512 threads. 4-stage cp.async fp32 staging, 2-buf bf16 convert.
// Warp mapping: 2 m-groups x 8 n-groups (2 m-tiles + 3..4 n-tiles per warp)
// -> fragment LDS traffic ~45% lower than 4m x 4n.
// ---------------------------------------------------------------------------
__global__ void __launch_bounds__(512, 1) gemm_partial(
    const float* __restrict__ x, const float* __restrict__ Wi)
{
    extern __shared__ float sm[];
    float* stgX = sm;                                       // 4 x 64x36 f32
    float* stgW = sm + 4 * (64 * XROW);                     // 4 x 32x200 f32
    uint32_t* cXh = (uint32_t*)(stgW + 4 * 6400);           // 2 x 64x18 b32
    uint32_t* cXl = cXh + 2 * 1152;
    uint32_t* cWh = cXl + 2 * 1152;                         // 2 x 200x18 b32
    uint32_t* cWl = cWh + 2 * 3600;

    const int t  = threadIdx.x;
    const int k0 = blockIdx.x * KC;
    const int kcnt = (K_TOTAL - k0 < KC) ? (K_TOTAL - k0) : KC;
    const int S = kcnt / KB;                                // 22 or 1

    const int warp = t >> 5, lane = t & 31;
    const int g = lane >> 2, tq = lane & 3;
    const int mg = warp >> 3;                               // 0..1 (2 m-tiles each)
    const int ng = warp & 7;                                // 0..7
    const int NT   = (ng == 0) ? 4 : 3;
    const int nbeg = (ng == 0) ? 0 : (4 + 3 * (ng - 1));    // 4+7*3 = 25 tiles

    float acc[2][4][4];
    #pragma unroll
    for (int a = 0; a < 2; a++)
        #pragma unroll
        for (int b = 0; b < 4; b++)
            #pragma unroll
            for (int c = 0; c < 4; c++) acc[a][b][c] = 0.f;

    auto issue_stage = [&](int step, int b4) {
        const int kg = k0 + step * KB;
        float* dX = stgX + b4 * (64 * XROW);
        float* dW = stgW + b4 * 6400;
        const float* sW = Wi + (size_t)kg * G4;
        for (int i = t; i < 1600; i += 512)
            cp_async16(dW + i * 4, sW + (size_t)i * 4);
        {   // 512 slots: row = t>>3, quad = t&7
            const int row = t >> 3, q = t & 7;
            cp_async16(dX + row * XROW + q * 4, x + (size_t)row * K_TOTAL + kg + q * 4);
        }
    };

    auto convert = [&](int b4, int b2) {
        // W: threads 0..399, n0 = t%200, half = t/200, 8 k-pairs each.
        if (t < 400) {
            const int n0 = t % 200;
            const int half = t / 200;
            const float* sWb = stgW + b4 * 6400 + half * 3200 + n0;
            uint32_t* whb = cWh + b2 * 3600 + n0 * 18 + half * 8;
            uint32_t* wlb = cWl + b2 * 3600 + n0 * 18 + half * 8;
            #pragma unroll
            for (int j = 0; j < 8; j++) {
                const float f0 = sWb[400 * j];
                const float f1 = sWb[400 * j + 200];
                const uint32_t hi = cvtpack(f1, f0);
                const float h0 = __uint_as_float(hi << 16);
                const float h1 = __uint_as_float(hi & 0xFFFF0000u);
                const uint32_t lo = cvtpack(f1 - h1, f0 - h0);
                whb[MSJ[j]] = hi;
                wlb[MSJ[j]] = lo;
            }
        }
        // X: threads 256..511, row = tx>>2, quarter q = tx&3, 4 k-pairs each.
        if (t >= 256) {
            const int tx = t - 256;
            const int row = tx >> 2, q = tx & 3;
            const float* sXb = stgX + b4 * (64 * XROW) + row * XROW + 8 * q;
            const int mbase = (q >> 1) * 8 + (q & 1);
            uint32_t* xhb = cXh + b2 * 1152 + row * 18 + mbase;
            uint32_t* xlb = cXl + b2 * 1152 + row * 18 + mbase;
            #pragma unroll
            for (int j = 0; j < 4; j++) {
                const float f0 = sXb[2 * j];
                const float f1 = sXb[2 * j + 1];
                const uint32_t hi = cvtpack(f1, f0);
                const float h0 = __uint_as_float(hi << 16);
                const float h1 = __uint_as_float(hi & 0xFFFF0000u);
                const uint32_t lo = cvtpack(f1 - h1, f0 - h0);
                xhb[2 * j] = hi;
                xlb[2 * j] = lo;
            }
        }
    };

    auto mma_tile = [&](int b2) {
        const uint32_t* xh = cXh + b2 * 1152; const uint32_t* xl = cXl + b2 * 1152;
        const uint32_t* wh = cWh + b2 * 3600; const uint32_t* wl = cWl + b2 * 3600;
        #pragma unroll
        for (int kb = 0; kb < 16; kb += 8) {
            uint2 Ah0[2], Ah1[2], Al0[2], Al1[2];
            #pragma unroll
            for (int m2 = 0; m2 < 2; m2++) {
                const int r0 = (mg * 2 + m2) * 16 + g;
                Ah0[m2] = *(const uint2*)(xh + r0 * 18 + kb + 2 * tq);
                Ah1[m2] = *(const uint2*)(xh + (r0 + 8) * 18 + kb + 2 * tq);
                Al0[m2] = *(const uint2*)(xl + r0 * 18 + kb + 2 * tq);
                Al1[m2] = *(const uint2*)(xl + (r0 + 8) * 18 + kb + 2 * tq);
            }
            #pragma unroll
            for (int i = 0; i < 4; i++) {
                if (i < NT) {
                    const int n = (nbeg + i) * 8 + g;
                    const uint2 Bh = *(const uint2*)(wh + n * 18 + kb + 2 * tq);
                    const uint2 Bl = *(const uint2*)(wl + n * 18 + kb + 2 * tq);
                    #pragma unroll
                    for (int m2 = 0; m2 < 2; m2++) {
                        mma16816(acc[m2][i], Ah0[m2].x, Ah1[m2].x, Ah0[m2].y, Ah1[m2].y, Bh.x, Bh.y);
                        mma16816(acc[m2][i], Ah0[m2].x, Ah1[m2].x, Ah0[m2].y, Ah1[m2].y, Bl.x, Bl.y);
                        mma16816(acc[m2][i], Al0[m2].x, Al1[m2].x, Al0[m2].y, Al1[m2].y, Bh.x, Bh.y);
                    }
                }
            }
        }
    };

    // ---- pipeline (4-stage, prefetch depth 3) ----
    issue_stage(0, 0);
    cp_commit();
    if (S > 1) issue_stage(1, 1);
    cp_commit();
    if (S > 2) issue_stage(2, 2);
    cp_commit();
    cp_wait2();                 // stage 0 landed
    __syncthreads();
    convert(0, 0);

    for (int s = 0; s < S; s++) {
        if (s + 3 < S) issue_stage(s + 3, (s + 3) & 3);
        cp_commit();
        cp_wait2();             // stage s+1 landed
        __syncthreads();        // conv writes of prev iter visible to mma
        if (s + 1 < S) convert((s + 1) & 3, (s + 1) & 1);
        mma_tile(s & 1);
    }

    // ---- epilogue ----
    float* pout = g_partial + (size_t)blockIdx.x * SG;
    #pragma unroll
    for (int m2 = 0; m2 < 2; m2++) {
        const int r0 = (mg * 2 + m2) * 16 + g;
        #pragma unroll
        for (int i = 0; i < 4; i++) {
            if (i < NT) {
                const int col = (nbeg + i) * 8 + 2 * tq;
                *(float2*)(pout + (size_t)r0 * G4 + col)       = make_float2(acc[m2][i][0], acc[m2][i][1]);
                *(float2*)(pout + (size_t)(r0 + 8) * G4 + col) = make_float2(acc[m2][i][2], acc[m2][i][3]);
            }
        }
    }
}

// ---------------------------------------------------------------------------
// Phase B: stage-1 split-K reduce (143 -> 16)
// ---------------------------------------------------------------------------
__global__ void reduce_stage1()
{
    const int idx = blockIdx.x * blockDim.x + threadIdx.x;
    const int grp = blockIdx.y;
    if (idx >= SG) return;
    const int b0   = grp * RSPAN;
    const int bend = (b0 + RSPAN < NB) ? (b0 + RSPAN) : NB;
    float s0 = 0.f, s1 = 0.f, s2 = 0.f, s3 = 0.f;
    int b = b0;
    for (; b + 3 < bend; b += 4) {
        s0 += g_partial[(size_t)(b + 0) * SG + idx];
        s1 += g_partial[(size_t)(b + 1) * SG + idx];
        s2 += g_partial[(size_t)(b + 2) * SG + idx];
        s3 += g_partial[(size_t)(b + 3) * SG + idx];
    }
    for (; b < bend; b++) s0 += g_partial[(size_t)b * SG + idx];
    g_p2[(size_t)grp * SG + idx] = (s0 + s1) + (s2 + s3);
}

// ---------------------------------------------------------------------------
// Phase C: LSTM producer/consumer with bar.arrive / bar.sync.
// 256 threads. Warps 0-6 (t<224): dot producers (t<200 active), weights in
// regs, arrive(bar1) / sync(bar2). Warp 7 (t>=224): activation consumer,
// lanes 0-24 own units (l, l+25); sync(bar1) / arrive(bar2).
// ---------------------------------------------------------------------------
__device__ __forceinline__ float tanh_fast(float v) {
    float r; asm("tanh.approx.f32 %0, %1;" : "=f"(r) : "f"(v)); return r;
}
__device__ __forceinline__ float sig_fast(float v) {
    return fmaf(0.5f, tanh_fast(0.5f * v), 0.5f);
}

__global__ void __launch_bounds__(256) lstm_kernel(const float* __restrict__ Wh,
                                                   const float* __restrict__ bi,
                                                   const float* __restrict__ bh,
                                                   float* __restrict__ out)
{
    extern __shared__ float sml[];
    float* gates_s = sml;                 // SG floats
    float* hbuf    = sml + SG;            // 64 floats (16B aligned)
    float* gbuf    = hbuf + 64;           // 200 floats
    const int t = threadIdx.x;

    // merged reduce (16 partials) + biases -> gates_s (all 8 warps)
    {
        const float4* src = (const float4*)g_p2;
        float4* dst = (float4*)gates_s;
        for (int i4 = t; i4 < SG / 4; i4 += 256) {
            float4 a0 = make_float4(0.f, 0.f, 0.f, 0.f);
            float4 a1 = a0, a2 = a0, a3 = a0;
            #pragma unroll
            for (int b = 0; b < RGROUPS; b += 4) {
                float4 v0 = src[(size_t)(b + 0) * (SG / 4) + i4];
                float4 v1 = src[(size_t)(b + 1) * (SG / 4) + i4];
                float4 v2 = src[(size_t)(b + 2) * (SG / 4) + i4];
                float4 v3 = src[(size_t)(b + 3) * (SG / 4) + i4];
                a0.x += v0.x; a0.y += v0.y; a0.z += v0.z; a0.w += v0.w;
                a1.x += v1.x; a1.y += v1.y; a1.z += v1.z; a1.w += v1.w;
                a2.x += v2.x; a2.y += v2.y; a2.z += v2.z; a2.w += v2.w;
                a3.x += v3.x; a3.y += v3.y; a3.z += v3.z; a3.w += v3.w;
            }
            const int gbase = (i4 * 4) % G4;
            const float4 bv1 = *(const float4*)(bi + gbase);
            const float4 bv2 = *(const float4*)(bh + gbase);
            float4 r;
            r.x = (a0.x + a1.x) + (a2.x + a3.x) + bv1.x + bv2.x;
            r.y = (a0.y + a1.y) + (a2.y + a3.y) + bv1.y + bv2.y;
            r.z = (a0.z + a1.z) + (a2.z + a3.z) + bv1.z + bv2.z;
            r.w = (a0.w + a1.w) + (a2.w + a3.w) + bv1.w + bv2.w;
            dst[i4] = r;
        }
    }

    ull wp[25];
    if (t < G4) {
        #pragma unroll
        for (int kk = 0; kk < 25; kk++) {
            float w0 = Wh[(2 * kk + 0) * G4 + t];
            float w1 = Wh[(2 * kk + 1) * G4 + t];
            wp[kk] = pack2(w0, w1);
        }
    }
    if (t < 64) hbuf[t] = 0.f;
    __syncthreads();

    if (t < 224) {
        // ---------------- producers (warps 0-6) ----------------
        for (int step = 0; step < SEQ; step++) {
            if (step > 0)
                asm volatile("bar.sync 2, 256;" ::: "memory");   // h(step) ready
            if (t < G4) {
                const float pre = gates_s[step * G4 + t];
                ull a0 = 0ull, a1 = 0ull, a2 = 0ull, a3 = 0ull;
                #pragma unroll
                for (int kk = 0; kk < 24; kk += 4) {
                    const ull h0 = *(const ull*)(hbuf + 2 * kk);
                    const ull h1 = *(const ull*)(hbuf + 2 * kk + 2);
                    const ull h2 = *(const ull*)(hbuf + 2 * kk + 4);
                    const ull h3 = *(const ull*)(hbuf + 2 * kk + 6);
                    fma2(a0, h0, wp[kk]);
                    fma2(a1, h1, wp[kk + 1]);
                    fma2(a2, h2, wp[kk + 2]);
                    fma2(a3, h3, wp[kk + 3]);
                }
                fma2(a0, *(const ull*)(hbuf + 48), wp[24]);
                const ull s = add2(add2(a0, a1), add2(a2, a3));
                gbuf[t] = pre + lo32(s) + hi32(s);
            }
            asm volatile("bar.arrive 1, 256;" ::: "memory");     // gbuf(step) done
        }
    } else {
        // ---------------- consumer (warp 7) ----------------
        const int l = t - 224;                // 0..31
        float c0 = 0.f, c1 = 0.f, h0 = 0.f, h1 = 0.f;
        for (int step = 0; step < SEQ; step++) {
            asm volatile("bar.sync 1, 256;" ::: "memory");       // gbuf(step) ready
            if (l < 25) {
                const int uA = l, uB = l + 25;
                const float iA = sig_fast(gbuf[uA]);
                const float fA = sig_fast(gbuf[50 + uA]);
                const float gA = tanh_fast(gbuf[100 + uA]);
                const float oA = sig_fast(gbuf[150 + uA]);
                const float iB = sig_fast(gbuf[uB]);
                const float fB = sig_fast(gbuf[50 + uB]);
                const float gB = tanh_fast(gbuf[100 + uB]);
                const float oB = sig_fast(gbuf[150 + uB]);
                c0 = fA * c0 + iA * gA;
                c1 = fB * c1 + iB * gB;
                h0 = oA * tanh_fast(c0);
                h1 = oB * tanh_fast(c1);
                hbuf[uA] = h0;
                hbuf[uB] = h1;
            }
            asm volatile("bar.arrive 2, 256;" ::: "memory");     // h(step+1) done
        }
        if (l < 25) { out[l] = h0; out[l + 25] = h1; }
    }
}

// ---------------------------------------------------------------------------
extern "C" void kernel_launch(void* const* d_in, const int* in_sizes, int n_in,
                              void* d_out, int out_size)
{
    const float* x  = (const float*)d_in[0];
    const float* Wi = (const float*)d_in[1];
    const float* bi = (const float*)d_in[2];
    const float* Wh = (const float*)d_in[3];
    const float* bh = (const float*)d_in[4];
    float* out = (float*)d_out;

    (void)in_sizes; (void)n_in; (void)out_size;

    const int gemm_smem = 4 * 64 * XROW * 4 + 4 * 6400 * 4
                        + (2 * 1152 * 2 + 2 * 3600 * 2) * 4;   // 215,296 B
    cudaFuncSetAttribute(gemm_partial, cudaFuncAttributeMaxDynamicSharedMemorySize,
                         gemm_smem);
    const int lstm_smem = (SG + 64 + 200) * 4 + 64;
    cudaFuncSetAttribute(lstm_kernel, cudaFuncAttributeMaxDynamicSharedMemorySize,
                         lstm_smem);

    gemm_partial<<<NB, 512, gemm_smem>>>(x, Wi);
    reduce_stage1<<<dim3(SG / 128, RGROUPS), 128>>>();
    lstm_kernel<<<1, 256, lstm_smem>>>(Wh, bi, bh, out);
}